// round 12
// baseline (speedup 1.0000x reference)
#include <cuda_runtime.h>
#include <cstdint>

// Dataset-fixed shapes: T=2048, N=4096, max_spikes=128.
#define NMAX   4096
#define TMAX   2048
#define CTAS   8
#define THRA   (NMAX / CTAS)      // 512 threads per phase-A CTA, 1 neuron/thread
#define CHUNK  32
#define NCMAX  (TMAX / CHUNK)     // 64 (covers worst case t0 = 0)
#define IDXINF 0x7FFFFFFFu

// Persistent state between phases (static device globals: no allocation).
static __device__ float g_sv[NMAX];
static __device__ float g_si[NMAX];
static __device__ float g_ss[NMAX];
static __device__ int   g_tstart;

// Phase-B scan scratch.
static __device__ float g_P[NCMAX * NMAX];
static __device__ float g_vstart[NCMAX * NMAX];
static __device__ float g_istart[NCMAX * NMAX];
static __device__ float g_ssum[NCMAX * NMAX];
static __device__ float g_sstart[NCMAX * NMAX];

__device__ __forceinline__ float sigmoid_acc(float x) {
    float e = expf(-x);
    float d = __fadd_rn(1.0f, e);
    return 1.0f / d;     // accurate: matches reference to ~1-2 ulp (validated)
}
__device__ __forceinline__ float sigmoid_fast(float x) {
    return __fdividef(1.0f, 1.0f + __expf(-x));   // phase B only (no thresholds)
}

__device__ __forceinline__ uint32_t smem_u32(const void* p) {
    uint32_t a;
    asm("{ .reg .u64 t; cvta.to.shared.u64 t, %1; cvt.u32.u64 %0, t; }"
        : "=r"(a) : "l"(p));
    return a;
}

__device__ __forceinline__ uint32_t mapa_u32(uint32_t local_addr, unsigned rank) {
    uint32_t remote;
    asm("mapa.shared::cluster.u32 %0, %1, %2;"
        : "=r"(remote) : "r"(local_addr), "r"(rank));
    return remote;
}

__device__ __forceinline__ void mbar_arrive_expect_tx(uint32_t mbar, unsigned tx) {
    asm volatile("mbarrier.arrive.expect_tx.shared.b64 _, [%0], %1;"
                 :: "r"(mbar), "r"(tx) : "memory");
}

// Push 4B into a peer CTA's smem slot and signal its mbarrier (tx += 4).
__device__ __forceinline__ void st_async_u32(uint32_t raddr, unsigned val, uint32_t rmbar) {
    asm volatile("st.async.shared::cluster.mbarrier::complete_tx::bytes.b32 [%0], %1, [%2];"
                 :: "r"(raddr), "r"(val), "r"(rmbar) : "memory");
}

// CTA-scope acquire (NOT cluster-scope): the slot data lands in OUR OWN smem
// via st.async and its visibility is ordered by this mbarrier's tx-completion.
// This matches the canonical consumer-wait pattern for async-proxy deliveries
// (ptx_helpers MBARRIER_WAIT_PARITY). The previous .acquire.cluster variant
// issues a cluster-scope fence per poll from every warp — suspected ~500cyc/step.
__device__ __forceinline__ void mbar_wait_parity(uint32_t mbar, unsigned parity) {
    unsigned done;
    do {
        asm volatile(
            "{\n\t.reg .pred p;\n\t"
            "mbarrier.try_wait.parity.acquire.cta.shared::cta.b64 p, [%1], %2;\n\t"
            "selp.b32 %0, 1, 0, p;\n\t}"
            : "=r"(done) : "r"(mbar), "r"(parity) : "memory");
    } while (!done);
}

// No-op kernel: 3 of these precede snn_phaseA so ncu's fixed window (harness
// prepends 2 launches; -s 5 -c 1 => our launch #4) captures snn_phaseA.
__global__ void snn_nop() {}

// ---------------------------------------------------------------------------
// Phase A: coupled event phase. 8-CTA cluster, 1 neuron/thread.
// Identical to the R10-passing kernel except the mbarrier wait scope
// (cluster -> cta). Exact-rounding ops in the reference's expression order.
// ---------------------------------------------------------------------------
__global__ void __cluster_dims__(CTAS, 1, 1) __launch_bounds__(THRA, 1)
snn_phaseA(const float* __restrict__ ts, const float* __restrict__ inp,
           const float* __restrict__ w, const float* __restrict__ v0,
           const float* __restrict__ i0, const float* __restrict__ mu,
           const float* __restrict__ s0u, const float* __restrict__ ru,
           const int* __restrict__ msp, float* __restrict__ out,
           int T, int N)
{
    __shared__ unsigned sh_warpmin[THRA / 32];
    __shared__ unsigned sh_slots[2][CTAS];              // [parity][src_rank]
    __shared__ alignas(8) unsigned long long sh_mbar;

    unsigned rank;
    asm("mov.u32 %0, %%cluster_ctarank;" : "=r"(rank));

    const int tid  = threadIdx.x;
    const int lane = tid & 31;
    const int wid  = tid >> 5;
    const int n    = (int)rank * THRA + tid;

    const float dt   = __fsub_rn(ts[1], ts[0]);
    const float mu1  = mu[0];
    const float nmu2 = -mu[1];
    const int max_spikes = msp[0];

    const uint32_t slots_addr = smem_u32(sh_slots);
    const uint32_t mbar_addr  = smem_u32((const void*)&sh_mbar);

    if (tid == 0) {
        asm volatile("mbarrier.init.shared.b64 [%0], %1;"
                     :: "r"(mbar_addr), "r"(1u) : "memory");
    }
    __syncthreads();
    asm volatile("barrier.cluster.arrive.aligned;" ::: "memory");
    asm volatile("barrier.cluster.wait.aligned;" ::: "memory");

    float v    = v0[n];                  // final v of previous step
    float iPre = i0[n];                  // i of previous step, w-add may be pending
    float s    = __fsub_rn(logf(__fadd_rn(s0u[n], 1e-12f)), 0.01f);
    bool  pend = false;
    float wv   = 0.0f;
    float cin  = inp[n];                 // inp row t = 0

    int nsp = 0;
    int t_end = T;

    for (int t = 0; t < T; ++t) {
        // Early independent loads (latency hidden across the step).
        const float ruv = ru[(size_t)t * N + n];
        const int   tn  = (t + 1 < T) ? t + 1 : T - 1;
        const float nin = inp[(size_t)tn * N + n];

        // Threshold state first — it feeds the inter-CTA reduction.
        const float sg   = sigmoid_acc(v);                    // sigmoid of OLD v
        const float sn0  = __fadd_rn(s, __fmul_rn(dt, sg));
        const bool  cross = (sn0 >= 0.0f);

        unsigned lm = cross ? (unsigned)n : IDXINF;
        lm = __reduce_min_sync(0xFFFFFFFFu, lm);
        if (lane == 0) sh_warpmin[wid] = lm;
        __syncthreads();
        if (wid == 0) {
            unsigned m = (lane < THRA / 32) ? sh_warpmin[lane] : IDXINF;
            m = __reduce_min_sync(0xFFFFFFFFu, m);
            if (lane == 0) mbar_arrive_expect_tx(mbar_addr, 4u * CTAS);
            if (lane < CTAS) {
                const uint32_t la = slots_addr + ((unsigned)(t & 1) * CTAS + rank) * 4u;
                st_async_u32(mapa_u32(la, (unsigned)lane), m,
                             mapa_u32(mbar_addr, (unsigned)lane));
            }
        }

        // ---- deferred finalization of step t-1 (off the sync critical path) ----
        const float ifin = pend ? __fadd_rn(iPre, wv) : iPre;
        if (t > 0) {
            float* op = out + ((size_t)(t - 1) * N + n) * 3;
            op[0] = v; op[1] = ifin; op[2] = s;
        }

        // Pre-fire values for step t.
        const float d1 = __fsub_rn(ifin, v);
        const float va = __fmul_rn(mu1, d1);
        const float vb = __fmul_rn(mu1, cin);
        float vn = __fadd_rn(v, __fmul_rn(dt, __fadd_rn(va, vb)));
        float in = __fadd_rn(ifin, __fmul_rn(dt, __fmul_rn(nmu2, ifin)));
        float sn = sn0;
        // Resample value: only crossing lanes ever consume it.
        float sjump = 0.0f;
        if (cross)
            sjump = __fsub_rn(logf(__fadd_rn(ruv, 1e-12f)), 0.01f);

        // Wait for all 8 candidates, gather from local smem.
        mbar_wait_parity(mbar_addr, (unsigned)(t & 1));
        unsigned idx = sh_slots[t & 1][0];
        #pragma unroll
        for (int r = 1; r < CTAS; ++r) idx = min(idx, sh_slots[t & 1][r]);

        const bool fire = (idx != IDXINF) && (nsp < max_spikes);
        pend = false;
        if (fire) {
            if (cross) {
                vn = __fsub_rn(vn, 1.0f);          // V_RESET
                sn = sjump;
            } else {
                pend = true;
                wv = w[(size_t)idx * N + n];       // DRAM load, ~1 step of slack
            }
            ++nsp;
        }

        v = vn; iPre = in; s = sn; cin = nin;
        if (nsp >= max_spikes) { t_end = t + 1; break; }    // cluster-uniform
    }

    // Epilogue: finalize and store the last computed row.
    const float ifin = pend ? __fadd_rn(iPre, wv) : iPre;
    {
        float* op = out + ((size_t)(t_end - 1) * N + n) * 3;
        op[0] = v; op[1] = ifin; op[2] = s;
    }
    g_sv[n] = v; g_si[n] = ifin; g_ss[n] = s;
    if (rank == 0 && tid == 0) g_tstart = t_end;
}

// ---------------------------------------------------------------------------
// Phase B (fire permanently false): blocked parallel scan over t.
//   v' = a*v + b*(i + inp_t);  i' = r*i;  s' = s + dt*sigmoid(v)
// Identical to the R9/R10-passing kernels.
// ---------------------------------------------------------------------------

// B1: per (chunk, neuron) input response P (v evolved from v=0, i=0).
__global__ void snn_B1(const float* __restrict__ ts, const float* __restrict__ inp,
                       const float* __restrict__ mu, int T, int N)
{
    const int n = blockIdx.x * blockDim.x + threadIdx.x;
    const int c = blockIdx.y;
    const int t0 = g_tstart;
    const int tb = t0 + c * CHUNK;
    if (n >= N || tb >= T) return;
    const int te = (tb + CHUNK < T) ? tb + CHUNK : T;

    const float dt = ts[1] - ts[0];
    const float a  = 1.0f - dt * mu[0];
    const float b  = dt * mu[0];

    float P = 0.0f;
    int t = tb;
    for (; t + 4 <= te; t += 4) {
        const float x0 = inp[(size_t)(t + 0) * N + n];
        const float x1 = inp[(size_t)(t + 1) * N + n];
        const float x2 = inp[(size_t)(t + 2) * N + n];
        const float x3 = inp[(size_t)(t + 3) * N + n];
        P = __fmaf_rn(a, P, b * x0);
        P = __fmaf_rn(a, P, b * x1);
        P = __fmaf_rn(a, P, b * x2);
        P = __fmaf_rn(a, P, b * x3);
    }
    for (; t < te; ++t)
        P = __fmaf_rn(a, P, b * inp[(size_t)t * N + n]);
    g_P[c * NMAX + n] = P;
}

// B2: per-neuron combine over chunks -> chunk-start (v, i).
__global__ void snn_B2(const float* __restrict__ ts, const float* __restrict__ mu,
                       int T, int N)
{
    const int n = blockIdx.x * blockDim.x + threadIdx.x;
    if (n >= N) return;
    const int t0 = g_tstart;
    if (t0 >= T) return;
    const int NC = (T - t0 + CHUNK - 1) / CHUNK;

    const float dt = ts[1] - ts[0];
    const float a  = 1.0f - dt * mu[0];
    const float b  = dt * mu[0];
    const float r  = 1.0f - dt * mu[1];

    // Full-chunk composed scalars: v_end = A*v0 + Q*i0 + P, i_end = R*i0.
    float A = 1.0f, Q = 0.0f, R = 1.0f;
    #pragma unroll 8
    for (int j = 0; j < CHUNK; ++j) { Q = a * Q + b * R; A *= a; R *= r; }

    float v = g_sv[n];
    float i = g_si[n];
    for (int c = 0; c < NC; ++c) {
        g_vstart[c * NMAX + n] = v;
        g_istart[c * NMAX + n] = i;
        if (c < NC - 1) {
            const float vn = A * v + Q * i + g_P[c * NMAX + n];
            i = R * i;
            v = vn;
        }
    }
}

// One fast step (sigmoid of OLD v); phase B only.
__device__ __forceinline__ void stepF(float dt, float mu1, float nmu2, float cin,
                                      float& v, float& i, float& spre)
{
    const float sg = sigmoid_fast(v);
    v = v + dt * (mu1 * (i - v) + mu1 * cin);
    i = i + dt * (nmu2 * i);
    spre = spre + dt * sg;
}

// B3a: simulate chunk -> per-chunk sigma sum only (no output traffic).
__global__ void snn_B3a(const float* __restrict__ ts, const float* __restrict__ inp,
                        const float* __restrict__ mu, int T, int N)
{
    const int n = blockIdx.x * blockDim.x + threadIdx.x;
    const int c = blockIdx.y;
    const int t0 = g_tstart;
    const int tb = t0 + c * CHUNK;
    if (n >= N || tb >= T) return;
    const int te = (tb + CHUNK < T) ? tb + CHUNK : T;

    const float dt   = ts[1] - ts[0];
    const float mu1  = mu[0];
    const float nmu2 = -mu[1];

    float v = g_vstart[c * NMAX + n];
    float i = g_istart[c * NMAX + n];
    float spre = 0.0f;

    int t = tb;
    for (; t + 4 <= te; t += 4) {
        const float x0 = inp[(size_t)(t + 0) * N + n];
        const float x1 = inp[(size_t)(t + 1) * N + n];
        const float x2 = inp[(size_t)(t + 2) * N + n];
        const float x3 = inp[(size_t)(t + 3) * N + n];
        stepF(dt, mu1, nmu2, x0, v, i, spre);
        stepF(dt, mu1, nmu2, x1, v, i, spre);
        stepF(dt, mu1, nmu2, x2, v, i, spre);
        stepF(dt, mu1, nmu2, x3, v, i, spre);
    }
    for (; t < te; ++t)
        stepF(dt, mu1, nmu2, inp[(size_t)t * N + n], v, i, spre);

    g_ssum[c * NMAX + n] = spre;
}

// B4: per-neuron scan of chunk sigma-sums -> chunk-start s.
__global__ void snn_B4(int T, int N)
{
    const int n = blockIdx.x * blockDim.x + threadIdx.x;
    if (n >= N) return;
    const int t0 = g_tstart;
    if (t0 >= T) return;
    const int NC = (T - t0 + CHUNK - 1) / CHUNK;

    float s = g_ss[n];
    for (int c = 0; c < NC; ++c) {
        g_sstart[c * NMAX + n] = s;
        s += g_ssum[c * NMAX + n];
    }
}

// B3b: re-simulate each chunk, write (v,i,s) as contiguous 12B records.
__global__ void snn_B3b(const float* __restrict__ ts, const float* __restrict__ inp,
                        const float* __restrict__ mu, float* __restrict__ out,
                        int T, int N)
{
    const int n = blockIdx.x * blockDim.x + threadIdx.x;
    const int c = blockIdx.y;
    const int t0 = g_tstart;
    const int tb = t0 + c * CHUNK;
    if (n >= N || tb >= T) return;
    const int te = (tb + CHUNK < T) ? tb + CHUNK : T;

    const float dt   = ts[1] - ts[0];
    const float mu1  = mu[0];
    const float nmu2 = -mu[1];

    float v = g_vstart[c * NMAX + n];
    float i = g_istart[c * NMAX + n];
    const float sstart = g_sstart[c * NMAX + n];
    float spre = 0.0f;

    int t = tb;
    for (; t + 4 <= te; t += 4) {
        const float x0 = inp[(size_t)(t + 0) * N + n];
        const float x1 = inp[(size_t)(t + 1) * N + n];
        const float x2 = inp[(size_t)(t + 2) * N + n];
        const float x3 = inp[(size_t)(t + 3) * N + n];

        stepF(dt, mu1, nmu2, x0, v, i, spre);
        float* op0 = out + ((size_t)(t + 0) * N + n) * 3;
        op0[0] = v; op0[1] = i; op0[2] = sstart + spre;

        stepF(dt, mu1, nmu2, x1, v, i, spre);
        float* op1 = out + ((size_t)(t + 1) * N + n) * 3;
        op1[0] = v; op1[1] = i; op1[2] = sstart + spre;

        stepF(dt, mu1, nmu2, x2, v, i, spre);
        float* op2 = out + ((size_t)(t + 2) * N + n) * 3;
        op2[0] = v; op2[1] = i; op2[2] = sstart + spre;

        stepF(dt, mu1, nmu2, x3, v, i, spre);
        float* op3 = out + ((size_t)(t + 3) * N + n) * 3;
        op3[0] = v; op3[1] = i; op3[2] = sstart + spre;
    }
    for (; t < te; ++t) {
        stepF(dt, mu1, nmu2, inp[(size_t)t * N + n], v, i, spre);
        float* op = out + ((size_t)t * N + n) * 3;
        op[0] = v; op[1] = i; op[2] = sstart + spre;
    }
}

// ---------------------------------------------------------------------------
extern "C" void kernel_launch(void* const* d_in, const int* in_sizes, int n_in,
                              void* d_out, int out_size)
{
    const float* ts  = (const float*)d_in[0];
    const float* inp = (const float*)d_in[1];
    const float* w   = (const float*)d_in[2];
    const float* v0  = (const float*)d_in[3];
    const float* i0  = (const float*)d_in[4];
    const float* mu  = (const float*)d_in[5];
    const float* s0u = (const float*)d_in[6];
    const float* ru  = (const float*)d_in[7];
    const int*   msp = (const int*)d_in[8];
    float* out = (float*)d_out;

    const int T = in_sizes[0];
    const int N = in_sizes[3];

    // 3 no-ops: harness prepends 2 launches, ncu uses -s 5 -c 1, so the
    // captured launch is ours #4 = snn_phaseA.
    snn_nop<<<1, 32>>>(); snn_nop<<<1, 32>>>(); snn_nop<<<1, 32>>>();

    snn_phaseA<<<CTAS, THRA>>>(ts, inp, w, v0, i0, mu, s0u, ru, msp, out, T, N);

    dim3 gB((N + 255) / 256, NCMAX);
    snn_B1 <<<gB, 256>>>(ts, inp, mu, T, N);
    snn_B2 <<<(N + 255) / 256, 256>>>(ts, mu, T, N);
    snn_B3a<<<gB, 256>>>(ts, inp, mu, T, N);
    snn_B4 <<<(N + 255) / 256, 256>>>(T, N);
    snn_B3b<<<gB, 256>>>(ts, inp, mu, out, T, N);
}

// round 13
// speedup vs baseline: 1.2471x; 1.2471x over previous
#include <cuda_runtime.h>
#include <cstdint>

// Dataset-fixed shapes: T=2048, N=4096, max_spikes=128.
#define NMAX   4096
#define TMAX   2048
#define CTAS   8
#define NPT    4                  // neurons per thread in phase A
#define THRA   128                // threads per phase-A CTA (4 warps)
#define NPC    (THRA * NPT)       // 512 neurons per CTA
#define CHUNK  32
#define NCMAX  (TMAX / CHUNK)     // 64 (covers worst case t0 = 0)
#define IDXINF 0x7FFFFFFFu

// Persistent state between phases (static device globals: no allocation).
static __device__ float g_sv[NMAX];
static __device__ float g_si[NMAX];
static __device__ float g_ss[NMAX];
static __device__ int   g_tstart;

// Phase-B scan scratch.
static __device__ float g_P[NCMAX * NMAX];
static __device__ float g_vstart[NCMAX * NMAX];
static __device__ float g_istart[NCMAX * NMAX];
static __device__ float g_ssum[NCMAX * NMAX];
static __device__ float g_sstart[NCMAX * NMAX];

__device__ __forceinline__ float sigmoid_acc(float x) {
    float e = expf(-x);
    float d = __fadd_rn(1.0f, e);
    return 1.0f / d;     // accurate: matches reference to ~1-2 ulp (validated)
}
__device__ __forceinline__ float sigmoid_fast(float x) {
    return __fdividef(1.0f, 1.0f + __expf(-x));   // phase B only (no thresholds)
}

__device__ __forceinline__ uint32_t smem_u32(const void* p) {
    uint32_t a;
    asm("{ .reg .u64 t; cvta.to.shared.u64 t, %1; cvt.u32.u64 %0, t; }"
        : "=r"(a) : "l"(p));
    return a;
}

__device__ __forceinline__ uint32_t mapa_u32(uint32_t local_addr, unsigned rank) {
    uint32_t remote;
    asm("mapa.shared::cluster.u32 %0, %1, %2;"
        : "=r"(remote) : "r"(local_addr), "r"(rank));
    return remote;
}

__device__ __forceinline__ void mbar_arrive_expect_tx(uint32_t mbar, unsigned tx) {
    asm volatile("mbarrier.arrive.expect_tx.shared.b64 _, [%0], %1;"
                 :: "r"(mbar), "r"(tx) : "memory");
}

// Push 4B into a peer CTA's smem slot and signal its mbarrier (tx += 4).
__device__ __forceinline__ void st_async_u32(uint32_t raddr, unsigned val, uint32_t rmbar) {
    asm volatile("st.async.shared::cluster.mbarrier::complete_tx::bytes.b32 [%0], %1, [%2];"
                 :: "r"(raddr), "r"(val), "r"(rmbar) : "memory");
}

// CTA-scope acquire. Only ONE warp per CTA ever executes this now, so the
// hot-poll MIO contention that 16 spinning warps caused (R12 profile:
// issue=22.4% of pure spin) is structurally gone.
__device__ __forceinline__ void mbar_wait_parity(uint32_t mbar, unsigned parity) {
    unsigned done;
    do {
        asm volatile(
            "{\n\t.reg .pred p;\n\t"
            "mbarrier.try_wait.parity.acquire.cta.shared::cta.b64 p, [%1], %2;\n\t"
            "selp.b32 %0, 1, 0, p;\n\t}"
            : "=r"(done) : "r"(mbar), "r"(parity) : "memory");
    } while (!done);
}

// No-op kernel: 3 of these precede snn_phaseA so ncu's fixed window (harness
// prepends 2 launches; -s 5 -c 1 => our launch #4) captures snn_phaseA.
__global__ void snn_nop() {}

// ---------------------------------------------------------------------------
// Phase A: coupled event phase. 8-CTA cluster, 128 threads (4 warps),
// 4 neurons/thread. Per-neuron math is op-for-op the validated R4/R9 sequence.
// Sync per step: warp-reduce -> smem -> bar #1 -> warp0 reduces + st.async
// mailbox to all 8 CTAs -> everyone does deferred work -> warp0 ALONE waits
// on the mbarrier and resolves idx -> bar #2 releases the other warps (parked
// at BAR: zero issue, zero MIO) -> apply fire.
// ---------------------------------------------------------------------------
__global__ void __cluster_dims__(CTAS, 1, 1) __launch_bounds__(THRA, 1)
snn_phaseA(const float* __restrict__ ts, const float* __restrict__ inp,
           const float* __restrict__ w, const float* __restrict__ v0,
           const float* __restrict__ i0, const float* __restrict__ mu,
           const float* __restrict__ s0u, const float* __restrict__ ru,
           const int* __restrict__ msp, float* __restrict__ out,
           int T, int N)
{
    __shared__ unsigned sh_warpmin[THRA / 32];          // 4
    __shared__ unsigned sh_slots[2][CTAS];              // [parity][src_rank]
    __shared__ unsigned sh_res;
    __shared__ alignas(8) unsigned long long sh_mbar;

    unsigned rank;
    asm("mov.u32 %0, %%cluster_ctarank;" : "=r"(rank));

    const int tid  = threadIdx.x;
    const int lane = tid & 31;
    const int wid  = tid >> 5;

    // Neuron indices: n_k = rank*512 + k*128 + tid  (coalesced per k).
    int nidx[NPT];
    #pragma unroll
    for (int k = 0; k < NPT; ++k) nidx[k] = (int)rank * NPC + k * THRA + tid;

    const float dt   = __fsub_rn(ts[1], ts[0]);
    const float mu1  = mu[0];
    const float nmu2 = -mu[1];
    const int max_spikes = msp[0];

    const uint32_t slots_addr = smem_u32(sh_slots);
    const uint32_t mbar_addr  = smem_u32((const void*)&sh_mbar);

    if (tid == 0) {
        asm volatile("mbarrier.init.shared.b64 [%0], %1;"
                     :: "r"(mbar_addr), "r"(1u) : "memory");
    }
    __syncthreads();
    asm volatile("barrier.cluster.arrive.aligned;" ::: "memory");
    asm volatile("barrier.cluster.wait.aligned;" ::: "memory");

    float v[NPT], iPre[NPT], s[NPT], wv[NPT], cin[NPT];
    bool  pend[NPT];
    #pragma unroll
    for (int k = 0; k < NPT; ++k) {
        v[k]    = v0[nidx[k]];
        iPre[k] = i0[nidx[k]];
        s[k]    = __fsub_rn(logf(__fadd_rn(s0u[nidx[k]], 1e-12f)), 0.01f);
        cin[k]  = inp[nidx[k]];
        pend[k] = false;
        wv[k]   = 0.0f;
    }

    int nsp = 0;
    int t_end = T;

    for (int t = 0; t < T; ++t) {
        // Early independent loads (latency hidden across the step).
        float ruv[NPT], nin[NPT];
        const int tn = (t + 1 < T) ? t + 1 : T - 1;
        #pragma unroll
        for (int k = 0; k < NPT; ++k) {
            ruv[k] = ru[(size_t)t * N + nidx[k]];
            nin[k] = inp[(size_t)tn * N + nidx[k]];
        }

        // Threshold state first — it feeds the inter-CTA reduction.
        float sn0[NPT];
        bool  cross[NPT];
        unsigned lm = IDXINF;
        #pragma unroll
        for (int k = 0; k < NPT; ++k) {
            const float sg = sigmoid_acc(v[k]);               // sigmoid of OLD v
            sn0[k]   = __fadd_rn(s[k], __fmul_rn(dt, sg));
            cross[k] = (sn0[k] >= 0.0f);
        }
        #pragma unroll
        for (int k = NPT - 1; k >= 0; --k)
            if (cross[k]) lm = (unsigned)nidx[k];
        lm = __reduce_min_sync(0xFFFFFFFFu, lm);
        if (lane == 0) sh_warpmin[wid] = lm;
        __syncthreads();                                      // bar #1
        if (wid == 0) {
            unsigned m = (lane < THRA / 32) ? sh_warpmin[lane] : IDXINF;
            m = __reduce_min_sync(0xFFFFFFFFu, m);
            if (lane == 0) mbar_arrive_expect_tx(mbar_addr, 4u * CTAS);
            if (lane < CTAS) {
                const uint32_t la = slots_addr + ((unsigned)(t & 1) * CTAS + rank) * 4u;
                st_async_u32(mapa_u32(la, (unsigned)lane), m,
                             mapa_u32(mbar_addr, (unsigned)lane));
            }
        }

        // ---- deferred finalization of step t-1 (off the sync critical path) ----
        float ifin[NPT];
        #pragma unroll
        for (int k = 0; k < NPT; ++k)
            ifin[k] = pend[k] ? __fadd_rn(iPre[k], wv[k]) : iPre[k];
        if (t > 0) {
            #pragma unroll
            for (int k = 0; k < NPT; ++k) {
                float* op = out + ((size_t)(t - 1) * N + nidx[k]) * 3;
                op[0] = v[k]; op[1] = ifin[k]; op[2] = s[k];
            }
        }

        // Pre-fire values for step t.
        float vn[NPT], in_[NPT], sn[NPT], sjump[NPT];
        #pragma unroll
        for (int k = 0; k < NPT; ++k) {
            const float d1 = __fsub_rn(ifin[k], v[k]);
            const float va = __fmul_rn(mu1, d1);
            const float vb = __fmul_rn(mu1, cin[k]);
            vn[k]  = __fadd_rn(v[k], __fmul_rn(dt, __fadd_rn(va, vb)));
            in_[k] = __fadd_rn(ifin[k], __fmul_rn(dt, __fmul_rn(nmu2, ifin[k])));
            sn[k]  = sn0[k];
            sjump[k] = 0.0f;
            if (cross[k])
                sjump[k] = __fsub_rn(logf(__fadd_rn(ruv[k], 1e-12f)), 0.01f);
        }

        // Warp 0 ALONE waits for all 8 candidates and resolves the argmin;
        // warps 1-3 park at bar #2 (no issue slots, no MIO pressure).
        if (wid == 0) {
            mbar_wait_parity(mbar_addr, (unsigned)(t & 1));
            unsigned m = (lane < CTAS) ? sh_slots[t & 1][lane] : IDXINF;
            m = __reduce_min_sync(0xFFFFFFFFu, m);
            if (lane == 0) sh_res = m;
        }
        __syncthreads();                                      // bar #2
        const unsigned idx = sh_res;

        const bool fire = (idx != IDXINF) && (nsp < max_spikes);
        #pragma unroll
        for (int k = 0; k < NPT; ++k) pend[k] = false;
        if (fire) {
            #pragma unroll
            for (int k = 0; k < NPT; ++k) {
                if (cross[k]) {
                    vn[k] = __fsub_rn(vn[k], 1.0f);    // V_RESET
                    sn[k] = sjump[k];
                } else {
                    pend[k] = true;
                    wv[k] = w[(size_t)idx * N + nidx[k]];  // DRAM, ~1 step slack
                }
            }
            ++nsp;
        }

        #pragma unroll
        for (int k = 0; k < NPT; ++k) {
            v[k] = vn[k]; iPre[k] = in_[k]; s[k] = sn[k]; cin[k] = nin[k];
        }
        if (nsp >= max_spikes) { t_end = t + 1; break; }      // cluster-uniform
    }

    // Epilogue: finalize and store the last computed row.
    #pragma unroll
    for (int k = 0; k < NPT; ++k) {
        const float ifin = pend[k] ? __fadd_rn(iPre[k], wv[k]) : iPre[k];
        float* op = out + ((size_t)(t_end - 1) * N + nidx[k]) * 3;
        op[0] = v[k]; op[1] = ifin; op[2] = s[k];
        g_sv[nidx[k]] = v[k]; g_si[nidx[k]] = ifin; g_ss[nidx[k]] = s[k];
    }
    if (rank == 0 && tid == 0) g_tstart = t_end;
}

// ---------------------------------------------------------------------------
// Phase B (fire permanently false): blocked parallel scan over t.
//   v' = a*v + b*(i + inp_t);  i' = r*i;  s' = s + dt*sigmoid(v)
// Identical to the R9/R10-passing kernels.
// ---------------------------------------------------------------------------

// B1: per (chunk, neuron) input response P (v evolved from v=0, i=0).
__global__ void snn_B1(const float* __restrict__ ts, const float* __restrict__ inp,
                       const float* __restrict__ mu, int T, int N)
{
    const int n = blockIdx.x * blockDim.x + threadIdx.x;
    const int c = blockIdx.y;
    const int t0 = g_tstart;
    const int tb = t0 + c * CHUNK;
    if (n >= N || tb >= T) return;
    const int te = (tb + CHUNK < T) ? tb + CHUNK : T;

    const float dt = ts[1] - ts[0];
    const float a  = 1.0f - dt * mu[0];
    const float b  = dt * mu[0];

    float P = 0.0f;
    int t = tb;
    for (; t + 4 <= te; t += 4) {
        const float x0 = inp[(size_t)(t + 0) * N + n];
        const float x1 = inp[(size_t)(t + 1) * N + n];
        const float x2 = inp[(size_t)(t + 2) * N + n];
        const float x3 = inp[(size_t)(t + 3) * N + n];
        P = __fmaf_rn(a, P, b * x0);
        P = __fmaf_rn(a, P, b * x1);
        P = __fmaf_rn(a, P, b * x2);
        P = __fmaf_rn(a, P, b * x3);
    }
    for (; t < te; ++t)
        P = __fmaf_rn(a, P, b * inp[(size_t)t * N + n]);
    g_P[c * NMAX + n] = P;
}

// B2: per-neuron combine over chunks -> chunk-start (v, i).
__global__ void snn_B2(const float* __restrict__ ts, const float* __restrict__ mu,
                       int T, int N)
{
    const int n = blockIdx.x * blockDim.x + threadIdx.x;
    if (n >= N) return;
    const int t0 = g_tstart;
    if (t0 >= T) return;
    const int NC = (T - t0 + CHUNK - 1) / CHUNK;

    const float dt = ts[1] - ts[0];
    const float a  = 1.0f - dt * mu[0];
    const float b  = dt * mu[0];
    const float r  = 1.0f - dt * mu[1];

    // Full-chunk composed scalars: v_end = A*v0 + Q*i0 + P, i_end = R*i0.
    float A = 1.0f, Q = 0.0f, R = 1.0f;
    #pragma unroll 8
    for (int j = 0; j < CHUNK; ++j) { Q = a * Q + b * R; A *= a; R *= r; }

    float v = g_sv[n];
    float i = g_si[n];
    for (int c = 0; c < NC; ++c) {
        g_vstart[c * NMAX + n] = v;
        g_istart[c * NMAX + n] = i;
        if (c < NC - 1) {
            const float vn = A * v + Q * i + g_P[c * NMAX + n];
            i = R * i;
            v = vn;
        }
    }
}

// One fast step (sigmoid of OLD v); phase B only.
__device__ __forceinline__ void stepF(float dt, float mu1, float nmu2, float cin,
                                      float& v, float& i, float& spre)
{
    const float sg = sigmoid_fast(v);
    v = v + dt * (mu1 * (i - v) + mu1 * cin);
    i = i + dt * (nmu2 * i);
    spre = spre + dt * sg;
}

// B3a: simulate chunk -> per-chunk sigma sum only (no output traffic).
__global__ void snn_B3a(const float* __restrict__ ts, const float* __restrict__ inp,
                        const float* __restrict__ mu, int T, int N)
{
    const int n = blockIdx.x * blockDim.x + threadIdx.x;
    const int c = blockIdx.y;
    const int t0 = g_tstart;
    const int tb = t0 + c * CHUNK;
    if (n >= N || tb >= T) return;
    const int te = (tb + CHUNK < T) ? tb + CHUNK : T;

    const float dt   = ts[1] - ts[0];
    const float mu1  = mu[0];
    const float nmu2 = -mu[1];

    float v = g_vstart[c * NMAX + n];
    float i = g_istart[c * NMAX + n];
    float spre = 0.0f;

    int t = tb;
    for (; t + 4 <= te; t += 4) {
        const float x0 = inp[(size_t)(t + 0) * N + n];
        const float x1 = inp[(size_t)(t + 1) * N + n];
        const float x2 = inp[(size_t)(t + 2) * N + n];
        const float x3 = inp[(size_t)(t + 3) * N + n];
        stepF(dt, mu1, nmu2, x0, v, i, spre);
        stepF(dt, mu1, nmu2, x1, v, i, spre);
        stepF(dt, mu1, nmu2, x2, v, i, spre);
        stepF(dt, mu1, nmu2, x3, v, i, spre);
    }
    for (; t < te; ++t)
        stepF(dt, mu1, nmu2, inp[(size_t)t * N + n], v, i, spre);

    g_ssum[c * NMAX + n] = spre;
}

// B4: per-neuron scan of chunk sigma-sums -> chunk-start s.
__global__ void snn_B4(int T, int N)
{
    const int n = blockIdx.x * blockDim.x + threadIdx.x;
    if (n >= N) return;
    const int t0 = g_tstart;
    if (t0 >= T) return;
    const int NC = (T - t0 + CHUNK - 1) / CHUNK;

    float s = g_ss[n];
    for (int c = 0; c < NC; ++c) {
        g_sstart[c * NMAX + n] = s;
        s += g_ssum[c * NMAX + n];
    }
}

// B3b: re-simulate each chunk, write (v,i,s) as contiguous 12B records.
__global__ void snn_B3b(const float* __restrict__ ts, const float* __restrict__ inp,
                        const float* __restrict__ mu, float* __restrict__ out,
                        int T, int N)
{
    const int n = blockIdx.x * blockDim.x + threadIdx.x;
    const int c = blockIdx.y;
    const int t0 = g_tstart;
    const int tb = t0 + c * CHUNK;
    if (n >= N || tb >= T) return;
    const int te = (tb + CHUNK < T) ? tb + CHUNK : T;

    const float dt   = ts[1] - ts[0];
    const float mu1  = mu[0];
    const float nmu2 = -mu[1];

    float v = g_vstart[c * NMAX + n];
    float i = g_istart[c * NMAX + n];
    const float sstart = g_sstart[c * NMAX + n];
    float spre = 0.0f;

    int t = tb;
    for (; t + 4 <= te; t += 4) {
        const float x0 = inp[(size_t)(t + 0) * N + n];
        const float x1 = inp[(size_t)(t + 1) * N + n];
        const float x2 = inp[(size_t)(t + 2) * N + n];
        const float x3 = inp[(size_t)(t + 3) * N + n];

        stepF(dt, mu1, nmu2, x0, v, i, spre);
        float* op0 = out + ((size_t)(t + 0) * N + n) * 3;
        op0[0] = v; op0[1] = i; op0[2] = sstart + spre;

        stepF(dt, mu1, nmu2, x1, v, i, spre);
        float* op1 = out + ((size_t)(t + 1) * N + n) * 3;
        op1[0] = v; op1[1] = i; op1[2] = sstart + spre;

        stepF(dt, mu1, nmu2, x2, v, i, spre);
        float* op2 = out + ((size_t)(t + 2) * N + n) * 3;
        op2[0] = v; op2[1] = i; op2[2] = sstart + spre;

        stepF(dt, mu1, nmu2, x3, v, i, spre);
        float* op3 = out + ((size_t)(t + 3) * N + n) * 3;
        op3[0] = v; op3[1] = i; op3[2] = sstart + spre;
    }
    for (; t < te; ++t) {
        stepF(dt, mu1, nmu2, inp[(size_t)t * N + n], v, i, spre);
        float* op = out + ((size_t)t * N + n) * 3;
        op[0] = v; op[1] = i; op[2] = sstart + spre;
    }
}

// ---------------------------------------------------------------------------
extern "C" void kernel_launch(void* const* d_in, const int* in_sizes, int n_in,
                              void* d_out, int out_size)
{
    const float* ts  = (const float*)d_in[0];
    const float* inp = (const float*)d_in[1];
    const float* w   = (const float*)d_in[2];
    const float* v0  = (const float*)d_in[3];
    const float* i0  = (const float*)d_in[4];
    const float* mu  = (const float*)d_in[5];
    const float* s0u = (const float*)d_in[6];
    const float* ru  = (const float*)d_in[7];
    const int*   msp = (const int*)d_in[8];
    float* out = (float*)d_out;

    const int T = in_sizes[0];
    const int N = in_sizes[3];

    // 3 no-ops: harness prepends 2 launches, ncu uses -s 5 -c 1, so the
    // captured launch is ours #4 = snn_phaseA.
    snn_nop<<<1, 32>>>(); snn_nop<<<1, 32>>>(); snn_nop<<<1, 32>>>();

    snn_phaseA<<<CTAS, THRA>>>(ts, inp, w, v0, i0, mu, s0u, ru, msp, out, T, N);

    dim3 gB((N + 255) / 256, NCMAX);
    snn_B1 <<<gB, 256>>>(ts, inp, mu, T, N);
    snn_B2 <<<(N + 255) / 256, 256>>>(ts, mu, T, N);
    snn_B3a<<<gB, 256>>>(ts, inp, mu, T, N);
    snn_B4 <<<(N + 255) / 256, 256>>>(T, N);
    snn_B3b<<<gB, 256>>>(ts, inp, mu, out, T, N);
}